// round 13
// baseline (speedup 1.0000x reference)
#include <cuda_runtime.h>
#include <cstddef>
#include <math_constants.h>

#define NNODES 4096
#define NB 4
#define BN (NNODES * NB)
#define DFEAT 240
#define FXSTRIDE 256
#define KNN 8
#define GS 20
#define GS3 (GS * GS * GS)

// Scratch (allocation-free rule: __device__ globals)
__device__ int    g_knn[BN * KNN];
__device__ float4 g_c4[BN];                       // (x,y,z,|c|^2/2)
__device__ float  g_fx[(size_t)BN * FXSTRIDE];    // repacked features
// Fused (W @ L) matrices, output scales baked in
__device__ float g_WL0[32 * 64];
__device__ float g_WL1a[64 * 32];
__device__ float g_WL1b[16 * 32];
__device__ float g_WL2[32 * 16];
// Spatial grid
__device__ unsigned g_bbox[NB][6];                // enc min xyz, enc max xyz
__device__ int      g_cnt[NB][GS3];
__device__ int      g_ctr[NB][GS3];
__device__ int      g_cellstart[NB][GS3 + 1];
__device__ unsigned short g_pcell[BN];            // per-point cell id (<8000)
__device__ float4   g_pts4[BN];                   // cell-sorted (x,y,z,|c|^2/2)
__device__ int      g_pidx[BN];                   // cell-sorted original flat id

__device__ __forceinline__ unsigned fenc(float f) {
    unsigned u = __float_as_uint(f);
    return (u & 0x80000000u) ? ~u : (u | 0x80000000u);
}
__device__ __forceinline__ float fdec(unsigned u) {
    return __uint_as_float((u & 0x80000000u) ? (u ^ 0x80000000u) : ~u);
}

// T[a][k] = (Cm[a] . ev)[k]
__device__ __forceinline__ void compute_T(float ex, float ey, float ez, float T[5][3]) {
    const float sc = 0.31622776601683794f;
    const float tc = 0.18257418583505536f;
    T[0][0] = sc * ey;  T[0][1] = sc * ex;   T[0][2] = 0.f;
    T[1][0] = sc * ez;  T[1][1] = 0.f;       T[1][2] = sc * ex;
    T[2][0] = 0.f;      T[2][1] = sc * ez;   T[2][2] = sc * ey;
    T[3][0] = sc * ex;  T[3][1] = -sc * ey;  T[3][2] = 0.f;
    T[4][0] = -tc * ex; T[4][1] = -tc * ey;  T[4][2] = 2.f * tc * ez;
}

// ============================================================================
// Kernel: fuse W@L matrices + init grid scratch (zero cnt/ctr, seed bbox).
// ============================================================================
__global__ __launch_bounds__(256) void fuse_kernel(
    const float* __restrict__ W1, const float* __restrict__ W2,
    const float* __restrict__ W3, const float* __restrict__ W4,
    const float* __restrict__ L0, const float* __restrict__ L1,
    const float* __restrict__ L2) {
    const float c1 = 0.11180339887498949f;
    const float c2 = 0.10206207261596575f;
    const float c3 = 0.39528470752104744f;
    const float c4 = 0.19364916731037085f;
    const float is32 = 0.17677669529663687f;
    int idx = blockIdx.x * 256 + threadIdx.x;
    // init grid scratch (grid-stride over 5120 threads)
    int* cntf = &g_cnt[0][0];
    int* ctrf = &g_ctr[0][0];
    for (int k = idx; k < NB * GS3; k += 5120) { cntf[k] = 0; ctrf[k] = 0; }
    if (idx < NB * 6) {
        int b = idx / 6, c = idx % 6;
        g_bbox[b][c] = (c < 3) ? 0xFFFFFFFFu : 0u;
    }
    if (idx < 2048) {                         // WL0 = W2@L0 : (32,64)
        int u = idx >> 6, w2 = idx & 63;
        float acc = 0.f;
        for (int w = 0; w < 64; w++) acc = fmaf(W2[u * 64 + w], L0[w * 64 + w2], acc);
        g_WL0[idx] = (c2 * 0.125f) * acc;
    } else if (idx < 4096) {                  // WL1a = W1@L1 : (64,32)
        int t = idx - 2048, u = t >> 5, w2 = t & 31;
        float acc = 0.f;
        for (int w = 0; w < 32; w++) acc = fmaf(W1[u * 32 + w], L1[w * 32 + w2], acc);
        g_WL1a[t] = (c1 * is32) * acc;
    } else if (idx < 4608) {                  // WL1b = W4@L1 : (16,32)
        int t = idx - 4096, u = t >> 5, w2 = t & 31;
        float acc = 0.f;
        for (int w = 0; w < 32; w++) acc = fmaf(W4[u * 32 + w], L1[w * 32 + w2], acc);
        g_WL1b[t] = (c4 * is32) * acc;
    } else if (idx < 5120) {                  // WL2 = W3@L2 : (32,16)
        int t = idx - 4608, u = t >> 4, w2 = t & 15;
        float acc = 0.f;
        for (int w = 0; w < 16; w++) acc = fmaf(W3[u * 16 + w], L2[w * 16 + w2], acc);
        g_WL2[t] = (c3 * 0.25f) * acc;
    }
}

// ============================================================================
// Kernel: repack features per node (warp per node) + build g_c4.
// ============================================================================
__global__ __launch_bounds__(256) void repack_kernel(
    const float* __restrict__ feats, const float* __restrict__ coords) {
    int warp = threadIdx.x >> 5, lane = threadIdx.x & 31;
    int node = blockIdx.x * 8 + warp;
    const float* f = feats + (size_t)node * DFEAT;
    float* o = g_fx + (size_t)node * FXSTRIDE;
    float4 A;
    A.x = f[lane];
    A.y = f[64 + 3 * lane];
    A.z = f[64 + 3 * lane + 1];
    A.w = f[64 + 3 * lane + 2];
    *(float4*)(o + 4 * lane) = A;
    o[128 + lane] = f[32 + lane];
    if (lane < 16) {
        float4 X;
        X.x = f[160 + 5 * lane];
        X.y = f[160 + 5 * lane + 1];
        X.z = f[160 + 5 * lane + 2];
        X.w = f[160 + 5 * lane + 3];
        *(float4*)(o + 160 + 4 * lane) = X;
        o[224 + lane] = f[160 + 5 * lane + 4];
    }
    if (threadIdx.x < 8) {
        int n2 = blockIdx.x * 8 + threadIdx.x;
        float x = coords[3 * n2], y = coords[3 * n2 + 1], z = coords[3 * n2 + 2];
        g_c4[n2] = make_float4(x, y, z, 0.5f * fmaf(x, x, fmaf(y, y, z * z)));
    }
}

// ============================================================================
// Grid build: bbox -> histogram -> prefix scan -> scatter (counting sort).
// ============================================================================
__global__ __launch_bounds__(256) void bbox_kernel(const float* __restrict__ coords) {
    const unsigned FULL = 0xffffffffu;
    int i = blockIdx.x * 256 + threadIdx.x;
    int b = i >> 12;
    float x = coords[3 * i], y = coords[3 * i + 1], z = coords[3 * i + 2];
    float mnx = x, mny = y, mnz = z, mxx = x, mxy = y, mxz = z;
#pragma unroll
    for (int off = 16; off >= 1; off >>= 1) {
        mnx = fminf(mnx, __shfl_xor_sync(FULL, mnx, off));
        mny = fminf(mny, __shfl_xor_sync(FULL, mny, off));
        mnz = fminf(mnz, __shfl_xor_sync(FULL, mnz, off));
        mxx = fmaxf(mxx, __shfl_xor_sync(FULL, mxx, off));
        mxy = fmaxf(mxy, __shfl_xor_sync(FULL, mxy, off));
        mxz = fmaxf(mxz, __shfl_xor_sync(FULL, mxz, off));
    }
    if ((threadIdx.x & 31) == 0) {            // warp never spans batches (4096%32==0)
        atomicMin(&g_bbox[b][0], fenc(mnx));
        atomicMin(&g_bbox[b][1], fenc(mny));
        atomicMin(&g_bbox[b][2], fenc(mnz));
        atomicMax(&g_bbox[b][3], fenc(mxx));
        atomicMax(&g_bbox[b][4], fenc(mxy));
        atomicMax(&g_bbox[b][5], fenc(mxz));
    }
}

__device__ __forceinline__ int cell_coord(float x, float x0, float ih) {
    int c = (int)((x - x0) * ih);
    return min(GS - 1, max(0, c));
}

__global__ __launch_bounds__(256) void hist_kernel(const float* __restrict__ coords) {
    int i = blockIdx.x * 256 + threadIdx.x;
    int b = i >> 12;
    float x0 = fdec(g_bbox[b][0]), y0 = fdec(g_bbox[b][1]), z0 = fdec(g_bbox[b][2]);
    float x1 = fdec(g_bbox[b][3]), y1 = fdec(g_bbox[b][4]), z1 = fdec(g_bbox[b][5]);
    float ihx = GS / (x1 - x0 + 1e-4f);
    float ihy = GS / (y1 - y0 + 1e-4f);
    float ihz = GS / (z1 - z0 + 1e-4f);
    float x = coords[3 * i], y = coords[3 * i + 1], z = coords[3 * i + 2];
    int cell = (cell_coord(z, z0, ihz) * GS + cell_coord(y, y0, ihy)) * GS
             + cell_coord(x, x0, ihx);
    g_pcell[i] = (unsigned short)cell;
    atomicAdd(&g_cnt[b][cell], 1);
}

__global__ __launch_bounds__(1024) void scan_kernel() {
    __shared__ int part[1024];
    int b = blockIdx.x, tid = threadIdx.x;
    int base = tid * 8;
    int loc[8];
    int s = 0;
#pragma unroll
    for (int k = 0; k < 8; k++) {
        int idx = base + k;
        loc[k] = s;
        s += (idx < GS3) ? g_cnt[b][idx] : 0;
    }
    part[tid] = s;
    __syncthreads();
    for (int off = 1; off < 1024; off <<= 1) {
        int v = (tid >= off) ? part[tid - off] : 0;
        __syncthreads();
        part[tid] += v;
        __syncthreads();
    }
    int excl = tid ? part[tid - 1] : 0;
#pragma unroll
    for (int k = 0; k < 8; k++) {
        int idx = base + k;
        if (idx < GS3) g_cellstart[b][idx] = excl + loc[k];
    }
    if (tid == 1023) g_cellstart[b][GS3] = part[1023];
}

__global__ __launch_bounds__(256) void scatter_kernel(const float* __restrict__ coords) {
    int i = blockIdx.x * 256 + threadIdx.x;
    int b = i >> 12;
    int cell = g_pcell[i];
    int pos = g_cellstart[b][cell] + atomicAdd(&g_ctr[b][cell], 1);
    float x = coords[3 * i], y = coords[3 * i + 1], z = coords[3 * i + 2];
    g_pts4[(b << 12) + pos] = make_float4(x, y, z, 0.5f * fmaf(x, x, fmaf(y, y, z * z)));
    g_pidx[(b << 12) + pos] = i;
}

// ============================================================================
// Kernel: grid kNN. WARP per query, TOP-9 across lanes 0..8 (lane 0 = self,
// which has the strict unique min score -|q|^2/2). Expanding cell rings;
// exact termination: stop at ring d when dist(q, boundary of scanned cube
// C_{d-1})^2 >= current 9th-best distance^2 (1e-3 slack for fp rounding).
// ============================================================================
__global__ __launch_bounds__(256) void knn_kernel() {
    const unsigned FULL = 0xffffffffu;
    int b = blockIdx.y;
    int warp = threadIdx.x >> 5, lane = threadIdx.x & 31;
    int q = blockIdx.x * 8 + warp;
    int qflat = (b << 12) + q;

    float4 qc = g_c4[qflat];
    float nqx = -qc.x, nqy = -qc.y, nqz = -qc.z;

    float x0 = fdec(g_bbox[b][0]), y0 = fdec(g_bbox[b][1]), z0 = fdec(g_bbox[b][2]);
    float x1 = fdec(g_bbox[b][3]), y1 = fdec(g_bbox[b][4]), z1 = fdec(g_bbox[b][5]);
    float ihx = GS / (x1 - x0 + 1e-4f);
    float ihy = GS / (y1 - y0 + 1e-4f);
    float ihz = GS / (z1 - z0 + 1e-4f);
    float hx = 1.f / ihx, hy = 1.f / ihy, hz = 1.f / ihz;
    int cx = cell_coord(qc.x, x0, ihx);
    int cy = cell_coord(qc.y, y0, ihy);
    int cz = cell_coord(qc.z, z0, ihz);

    const float4* pts = g_pts4 + (b << 12);
    const int* pidx = g_pidx + (b << 12);
    const int* cs = g_cellstart[b];

    float v = CUDART_INF_F;
    int  vid = 0x7fffffff;
    float worst = CUDART_INF_F;

    auto span = [&](int s0, int s1) {
        for (int base = s0; base < s1; base += 32) {
            int j = base + lane;
            float sv = CUDART_INF_F;
            int id = 0;
            if (j < s1) {
                float4 c = pts[j];
                sv = fmaf(nqx, c.x, fmaf(nqy, c.y, fmaf(nqz, c.z, c.w)));
                id = pidx[j];
            }
            unsigned mask = __ballot_sync(FULL, sv < worst);
            while (mask) {
                int src = __ffs(mask) - 1; mask &= mask - 1;
                float nb = __shfl_sync(FULL, sv, src);
                if (nb < worst) {
                    int ib = __shfl_sync(FULL, id, src);
                    unsigned gt = __ballot_sync(FULL, (lane < 9) && (v > nb));
                    int p = __ffs(gt) - 1;
                    float vup = __shfl_up_sync(FULL, v, 1);
                    int  iup  = __shfl_up_sync(FULL, vid, 1);
                    if (lane == p)                 { v = nb;  vid = ib;  }
                    else if (lane > p && lane < 9) { v = vup; vid = iup; }
                    worst = __shfl_sync(FULL, v, 8);
                }
            }
        }
    };

    {   // ring 0: own cell
        int c0 = (cz * GS + cy) * GS + cx;
        span(cs[c0], cs[c0 + 1]);
    }

    for (int d = 1; d <= GS; d++) {
        // lower bound on distance to anything outside scanned cube C_{d-1}
        int dm = d - 1;
        float bnd = CUDART_INF_F;
        if (cx - dm > 0)      bnd = fminf(bnd, qc.x - (x0 + (cx - dm) * hx));
        if (cx + dm < GS - 1) bnd = fminf(bnd, (x0 + (cx + dm + 1) * hx) - qc.x);
        if (cy - dm > 0)      bnd = fminf(bnd, qc.y - (y0 + (cy - dm) * hy));
        if (cy + dm < GS - 1) bnd = fminf(bnd, (y0 + (cy + dm + 1) * hy) - qc.y);
        if (cz - dm > 0)      bnd = fminf(bnd, qc.z - (z0 + (cz - dm) * hz));
        if (cz + dm < GS - 1) bnd = fminf(bnd, (z0 + (cz + dm + 1) * hz) - qc.z);
        if (bnd == CUDART_INF_F) break;           // scanned cube covers whole grid
        bnd = fmaxf(0.f, bnd - 1e-3f);            // fp slack
        float wd2 = 2.f * worst + 2.f * qc.w;     // worst squared distance
        if (bnd * bnd >= wd2) break;

        for (int dz = -d; dz <= d; dz++) {
            int cz2 = cz + dz;
            if (cz2 < 0 || cz2 >= GS) continue;
            int adz = abs(dz);
            for (int dy = -d; dy <= d; dy++) {
                int cy2 = cy + dy;
                if (cy2 < 0 || cy2 >= GS) continue;
                int rowbase = (cz2 * GS + cy2) * GS;
                if (adz == d || abs(dy) == d) {   // full row
                    int xlo = max(0, cx - d), xhi = min(GS - 1, cx + d);
                    span(cs[rowbase + xlo], cs[rowbase + xhi + 1]);
                } else {                          // just the two x-extremes
                    if (cx - d >= 0) { int id = rowbase + cx - d; span(cs[id], cs[id + 1]); }
                    if (cx + d < GS) { int id = rowbase + cx + d; span(cs[id], cs[id + 1]); }
                }
            }
        }
    }

    if (lane >= 1 && lane < 9)                    // lane 0 = self; drop it
        g_knn[qflat * KNN + (lane - 1)] = vid;    // vid already flat across batches
}

// ============================================================================
// Kernel: fused aggregation (unchanged from round 12).
// ============================================================================
__global__ __launch_bounds__(256) void agg_kernel(float* __restrict__ out) {
    __shared__ float sWL0[2048], sWL1a[2048], sWL1b[512], sWL2[512];
    __shared__ float sag[8][512];
    for (int k = threadIdx.x; k < 2048; k += 256) { sWL0[k] = g_WL0[k]; sWL1a[k] = g_WL1a[k]; }
    for (int k = threadIdx.x; k < 512;  k += 256) { sWL1b[k] = g_WL1b[k]; sWL2[k] = g_WL2[k]; }

    const unsigned FULL = 0xffffffffu;
    int warp = threadIdx.x >> 5, lane = threadIdx.x & 31;
    int node = (blockIdx.x << 3) + warp;
    float4 qc = g_c4[node];

    int4 n0 = *(const int4*)(g_knn + node * KNN);
    int4 n1 = *(const int4*)(g_knn + node * KNN + 4);
    int nbr[8] = {n0.x, n0.y, n0.z, n0.w, n1.x, n1.y, n1.z, n1.w};
    float ex[8], ey[8], ez[8];
#pragma unroll
    for (int r = 0; r < 8; r++) {
        float4 cn = g_c4[nbr[r]];
        ex[r] = cn.x - qc.x;
        ey[r] = cn.y - qc.y;
        ez[r] = cn.z - qc.z;
    }

    float a0 = 0.f;
    float a1a0[3] = {0.f, 0.f, 0.f};
    float a1a1[3] = {0.f, 0.f, 0.f};
    float a1b[3]  = {0.f, 0.f, 0.f};
    float a2[5]   = {0.f, 0.f, 0.f, 0.f, 0.f};

#pragma unroll
    for (int r = 0; r < KNN; r++) {
        const float* f = g_fx + (size_t)nbr[r] * FXSTRIDE;
        float4 A = *(const float4*)(f + 4 * lane);
        float f0b = f[128 + lane];
        float4 X = make_float4(0.f, 0.f, 0.f, 0.f);
        float x4 = 0.f;
        if (lane < 16) {
            X  = *(const float4*)(f + 160 + 4 * lane);
            x4 = f[224 + lane];
        }

        float T[5][3];
        compute_T(ex[r], ey[r], ez[r], T);
        float e[3] = {ex[r], ey[r], ez[r]};
        float x1v[3] = {A.y, A.z, A.w};
        float x2v[5] = {X.x, X.y, X.z, X.w, x4};

#pragma unroll
        for (int k = 0; k < 3; k++) {
            a1a0[k] = fmaf(A.x, e[k], a1a0[k]);
            a1a1[k] = fmaf(f0b, e[k], a1a1[k]);
        }
#pragma unroll
        for (int i = 0; i < 3; i++) a0 = fmaf(x1v[i], e[i], a0);
#pragma unroll
        for (int a = 0; a < 5; a++)
#pragma unroll
            for (int i = 0; i < 3; i++) a2[a] = fmaf(x1v[i], T[a][i], a2[a]);
        if (lane < 16) {
#pragma unroll
            for (int a = 0; a < 5; a++)
#pragma unroll
                for (int k = 0; k < 3; k++) a1b[k] = fmaf(x2v[a], T[a][k], a1b[k]);
        }
    }

    __syncthreads();

    float* ag = sag[warp];
    ag[lane] = a0;
#pragma unroll
    for (int k = 0; k < 3; k++) {
        ag[32 + 4 * lane + k]        = a1a0[k];
        ag[32 + 4 * (lane + 32) + k] = a1a1[k];
    }
    if (lane < 16) {
#pragma unroll
        for (int k = 0; k < 3; k++) ag[288 + 4 * lane + k] = a1b[k];
    }
#pragma unroll
    for (int a = 0; a < 5; a++) ag[352 + 5 * lane + a] = a2[a];
    __syncwarp();

    float* o = out + (size_t)node * DFEAT;
    {
        float y0 = 0.f, y1v = 0.f;
#pragma unroll
        for (int u4 = 0; u4 < 8; u4++) {
            float4 av = *(const float4*)(ag + 4 * u4);
            float a4[4] = {av.x, av.y, av.z, av.w};
#pragma unroll
            for (int j = 0; j < 4; j++) {
                float2 w2 = *(const float2*)(sWL0 + (4 * u4 + j) * 64 + 2 * lane);
                y0  = fmaf(a4[j], w2.x, y0);
                y1v = fmaf(a4[j], w2.y, y1v);
            }
        }
        o[2 * lane]     = y0;
        o[2 * lane + 1] = y1v;
    }
    {
        float y[3] = {0.f, 0.f, 0.f};
#pragma unroll
        for (int u = 0; u < 64; u++) {
            float4 av = *(const float4*)(ag + 32 + 4 * u);
            float lw = sWL1a[u * 32 + lane];
            y[0] = fmaf(av.x, lw, y[0]);
            y[1] = fmaf(av.y, lw, y[1]);
            y[2] = fmaf(av.z, lw, y[2]);
        }
#pragma unroll
        for (int u = 0; u < 16; u++) {
            float4 av = *(const float4*)(ag + 288 + 4 * u);
            float lw = sWL1b[u * 32 + lane];
            y[0] = fmaf(av.x, lw, y[0]);
            y[1] = fmaf(av.y, lw, y[1]);
            y[2] = fmaf(av.z, lw, y[2]);
        }
#pragma unroll
        for (int k = 0; k < 3; k++) o[64 + 3 * lane + k] = y[k];
    }
    {
        int w2i = lane & 15, half = lane >> 4;
        float y[5] = {0.f, 0.f, 0.f, 0.f, 0.f};
#pragma unroll
        for (int uu = 0; uu < 16; uu++) {
            int u = half * 16 + uu;
            float lw = sWL2[u * 16 + w2i];
#pragma unroll
            for (int a = 0; a < 5; a++) y[a] = fmaf(ag[352 + 5 * u + a], lw, y[a]);
        }
#pragma unroll
        for (int a = 0; a < 5; a++) {
            y[a] += __shfl_xor_sync(FULL, y[a], 16);
            if (lane < 16) o[160 + 5 * lane + a] = y[a];
        }
    }
}

// ============================================================================
extern "C" void kernel_launch(void* const* d_in, const int* in_sizes, int n_in,
                              void* d_out, int out_size) {
    const float* feats  = (const float*)d_in[0];
    const float* coords = (const float*)d_in[1];
    const float* W1 = (const float*)d_in[2];
    const float* W2 = (const float*)d_in[3];
    const float* W3 = (const float*)d_in[4];
    const float* W4 = (const float*)d_in[5];
    const float* L0 = (const float*)d_in[6];
    const float* L1 = (const float*)d_in[7];
    const float* L2 = (const float*)d_in[8];
    float* out = (float*)d_out;

    fuse_kernel<<<20, 256>>>(W1, W2, W3, W4, L0, L1, L2);  // also inits grid scratch
    repack_kernel<<<BN / 8, 256>>>(feats, coords);
    bbox_kernel<<<BN / 256, 256>>>(coords);
    hist_kernel<<<BN / 256, 256>>>(coords);
    scan_kernel<<<NB, 1024>>>();
    scatter_kernel<<<BN / 256, 256>>>(coords);
    knn_kernel<<<dim3(NNODES / 8, NB), 256>>>();
    agg_kernel<<<BN / 8, 256>>>(out);
}

// round 14
// speedup vs baseline: 1.2712x; 1.2712x over previous
#include <cuda_runtime.h>
#include <cstddef>
#include <math_constants.h>

#define NNODES 4096
#define NB 4
#define BN (NNODES * NB)
#define DFEAT 240
#define FXSTRIDE 256
#define KNN 8
#define KTHREADS 512

// Scratch (allocation-free rule: __device__ globals)
__device__ int    g_knn[BN * KNN];
__device__ float4 g_c4[BN];                       // (x,y,z,|c|^2/2)
__device__ float  g_fx[(size_t)BN * FXSTRIDE];    // repacked features
// Fused (W @ L) matrices, output scales baked in
__device__ float g_WL0[32 * 64];
__device__ float g_WL1a[64 * 32];
__device__ float g_WL1b[16 * 32];
__device__ float g_WL2[32 * 16];

// T[a][k] = (Cm[a] . ev)[k]
__device__ __forceinline__ void compute_T(float ex, float ey, float ez, float T[5][3]) {
    const float sc = 0.31622776601683794f;
    const float tc = 0.18257418583505536f;
    T[0][0] = sc * ey;  T[0][1] = sc * ex;   T[0][2] = 0.f;
    T[1][0] = sc * ez;  T[1][1] = 0.f;       T[1][2] = sc * ex;
    T[2][0] = 0.f;      T[2][1] = sc * ez;   T[2][2] = sc * ey;
    T[3][0] = sc * ex;  T[3][1] = -sc * ey;  T[3][2] = 0.f;
    T[4][0] = -tc * ex; T[4][1] = -tc * ey;  T[4][2] = 2.f * tc * ez;
}

// ============================================================================
// Kernel 0: repack features per node (warp per node) + build g_c4.
// ============================================================================
__global__ __launch_bounds__(256) void repack_kernel(
    const float* __restrict__ feats, const float* __restrict__ coords) {
    int warp = threadIdx.x >> 5, lane = threadIdx.x & 31;
    int node = blockIdx.x * 8 + warp;
    const float* f = feats + (size_t)node * DFEAT;
    float* o = g_fx + (size_t)node * FXSTRIDE;
    float4 A;
    A.x = f[lane];
    A.y = f[64 + 3 * lane];
    A.z = f[64 + 3 * lane + 1];
    A.w = f[64 + 3 * lane + 2];
    *(float4*)(o + 4 * lane) = A;
    o[128 + lane] = f[32 + lane];
    if (lane < 16) {
        float4 X;
        X.x = f[160 + 5 * lane];
        X.y = f[160 + 5 * lane + 1];
        X.z = f[160 + 5 * lane + 2];
        X.w = f[160 + 5 * lane + 3];
        *(float4*)(o + 160 + 4 * lane) = X;
        o[224 + lane] = f[160 + 5 * lane + 4];
    }
    if (threadIdx.x < 8) {
        int n2 = blockIdx.x * 8 + threadIdx.x;
        float x = coords[3 * n2], y = coords[3 * n2 + 1], z = coords[3 * n2 + 2];
        g_c4[n2] = make_float4(x, y, z, 0.5f * fmaf(x, x, fmaf(y, y, z * z)));
    }
}

// ============================================================================
// Kernel 1: kNN, 4 QUERIES per warp. Each lane loads ONE candidate float4 per
// step and scores it against all 4 queries (smem wavefronts amortized 4x —
// the measured L1 bottleneck). Four independent TOP-9s live in lanes 0..8
// (sorted ascending, lane 8 = worst). No self-exclusion: the query itself has
// the strict unique min score (-|q|^2/2), lands in lane 0; lanes 1..8 = true
// top-8. Candidate id recovered arithmetically from the ballot lane. Tie =
// earliest index (ballot low->high = index order) — matches jax.lax.top_k.
// ============================================================================
__global__ __launch_bounds__(KTHREADS) void knn_kernel() {
    __shared__ float4 tile[2048];                 // 32KB (chunked: 2 x 2048)
    const unsigned FULL = 0xffffffffu;
    int b = blockIdx.y;
    int warp = threadIdx.x >> 5, lane = threadIdx.x & 31;
    int qbase = (blockIdx.x * 16 + warp) * 4;     // 4 consecutive queries
    int qfbase = b * NNODES + qbase;

    float nqx[4], nqy[4], nqz[4], v[4], worst[4];
    int vid[4];
#pragma unroll
    for (int qi = 0; qi < 4; qi++) {
        float4 qc = g_c4[qfbase + qi];
        nqx[qi] = -qc.x; nqy[qi] = -qc.y; nqz[qi] = -qc.z;
        v[qi] = CUDART_INF_F; vid[qi] = 0x7fffffff; worst[qi] = CUDART_INF_F;
    }

    for (int ch = 0; ch < 2; ch++) {
        int cbase = ch << 11;
        __syncthreads();
        for (int k = threadIdx.x; k < 2048; k += KTHREADS)
            tile[k] = g_c4[b * NNODES + cbase + k];
        __syncthreads();

        for (int s = 0; s < 2048; s += 32) {
            float4 c = tile[s + lane];            // one candidate per lane
            float sq[4];
#pragma unroll
            for (int qi = 0; qi < 4; qi++)
                sq[qi] = fmaf(nqx[qi], c.x, fmaf(nqy[qi], c.y, fmaf(nqz[qi], c.z, c.w)));

            bool pass = (sq[0] < worst[0]) | (sq[1] < worst[1])
                      | (sq[2] < worst[2]) | (sq[3] < worst[3]);
            if (__any_sync(FULL, pass)) {
                int j0 = b * NNODES + cbase + s;  // flat id of lane-0 candidate
#pragma unroll
                for (int qi = 0; qi < 4; qi++) {
                    unsigned mask = __ballot_sync(FULL, sq[qi] < worst[qi]);
                    while (mask) {
                        int src = __ffs(mask) - 1; mask &= mask - 1;
                        float nb = __shfl_sync(FULL, sq[qi], src);
                        if (nb < worst[qi]) {             // warp-uniform recheck
                            int ib = j0 + src;            // arithmetic id recovery
                            unsigned gt = __ballot_sync(FULL, (lane < 9) && (v[qi] > nb));
                            int p = __ffs(gt) - 1;        // nonzero: lane8 holds worst>nb
                            float vup = __shfl_up_sync(FULL, v[qi], 1);
                            int  iup  = __shfl_up_sync(FULL, vid[qi], 1);
                            if (lane == p)                 { v[qi] = nb;  vid[qi] = ib;  }
                            else if (lane > p && lane < 9) { v[qi] = vup; vid[qi] = iup; }
                            worst[qi] = __shfl_sync(FULL, v[qi], 8);
                        }
                    }
                }
            }
        }
    }

#pragma unroll
    for (int qi = 0; qi < 4; qi++) {
        if (lane >= 1 && lane < 9)                // lane 0 = self; drop it
            g_knn[(qfbase + qi) * KNN + (lane - 1)] = vid[qi];
    }
}

// ============================================================================
// Kernel 2: fuse W and L matrices (W commutes with aggregation) + bake scales.
// ============================================================================
__global__ __launch_bounds__(256) void fuse_kernel(
    const float* __restrict__ W1, const float* __restrict__ W2,
    const float* __restrict__ W3, const float* __restrict__ W4,
    const float* __restrict__ L0, const float* __restrict__ L1,
    const float* __restrict__ L2) {
    const float c1 = 0.11180339887498949f;
    const float c2 = 0.10206207261596575f;
    const float c3 = 0.39528470752104744f;
    const float c4 = 0.19364916731037085f;
    const float is32 = 0.17677669529663687f;
    int idx = blockIdx.x * 256 + threadIdx.x;
    if (idx < 2048) {                         // WL0 = W2@L0 : (32,64)
        int u = idx >> 6, w2 = idx & 63;
        float acc = 0.f;
        for (int w = 0; w < 64; w++) acc = fmaf(W2[u * 64 + w], L0[w * 64 + w2], acc);
        g_WL0[idx] = (c2 * 0.125f) * acc;
    } else if (idx < 4096) {                  // WL1a = W1@L1 : (64,32)
        int t = idx - 2048, u = t >> 5, w2 = t & 31;
        float acc = 0.f;
        for (int w = 0; w < 32; w++) acc = fmaf(W1[u * 32 + w], L1[w * 32 + w2], acc);
        g_WL1a[t] = (c1 * is32) * acc;
    } else if (idx < 4608) {                  // WL1b = W4@L1 : (16,32)
        int t = idx - 4096, u = t >> 5, w2 = t & 31;
        float acc = 0.f;
        for (int w = 0; w < 32; w++) acc = fmaf(W4[u * 32 + w], L1[w * 32 + w2], acc);
        g_WL1b[t] = (c4 * is32) * acc;
    } else {                                  // WL2 = W3@L2 : (32,16)
        int t = idx - 4608, u = t >> 4, w2 = t & 15;
        float acc = 0.f;
        for (int w = 0; w < 16; w++) acc = fmaf(W3[u * 16 + w], L2[w * 16 + w2], acc);
        g_WL2[t] = (c3 * 0.25f) * acc;
    }
}

// ============================================================================
// Kernel 3: fused aggregation (round-12 version, measured-stable 47us).
// ============================================================================
__global__ __launch_bounds__(256) void agg_kernel(float* __restrict__ out) {
    __shared__ float sWL0[2048], sWL1a[2048], sWL1b[512], sWL2[512];
    __shared__ float sag[8][512];
    for (int k = threadIdx.x; k < 2048; k += 256) { sWL0[k] = g_WL0[k]; sWL1a[k] = g_WL1a[k]; }
    for (int k = threadIdx.x; k < 512;  k += 256) { sWL1b[k] = g_WL1b[k]; sWL2[k] = g_WL2[k]; }

    const unsigned FULL = 0xffffffffu;
    int warp = threadIdx.x >> 5, lane = threadIdx.x & 31;
    int node = (blockIdx.x << 3) + warp;
    float4 qc = g_c4[node];

    int4 n0 = *(const int4*)(g_knn + node * KNN);
    int4 n1 = *(const int4*)(g_knn + node * KNN + 4);
    int nbr[8] = {n0.x, n0.y, n0.z, n0.w, n1.x, n1.y, n1.z, n1.w};
    float ex[8], ey[8], ez[8];
#pragma unroll
    for (int r = 0; r < 8; r++) {
        float4 cn = g_c4[nbr[r]];
        ex[r] = cn.x - qc.x;
        ey[r] = cn.y - qc.y;
        ez[r] = cn.z - qc.z;
    }

    float a0 = 0.f;
    float a1a0[3] = {0.f, 0.f, 0.f};
    float a1a1[3] = {0.f, 0.f, 0.f};
    float a1b[3]  = {0.f, 0.f, 0.f};
    float a2[5]   = {0.f, 0.f, 0.f, 0.f, 0.f};

#pragma unroll
    for (int r = 0; r < KNN; r++) {
        const float* f = g_fx + (size_t)nbr[r] * FXSTRIDE;
        float4 A = *(const float4*)(f + 4 * lane);
        float f0b = f[128 + lane];
        float4 X = make_float4(0.f, 0.f, 0.f, 0.f);
        float x4 = 0.f;
        if (lane < 16) {
            X  = *(const float4*)(f + 160 + 4 * lane);
            x4 = f[224 + lane];
        }

        float T[5][3];
        compute_T(ex[r], ey[r], ez[r], T);
        float e[3] = {ex[r], ey[r], ez[r]};
        float x1v[3] = {A.y, A.z, A.w};
        float x2v[5] = {X.x, X.y, X.z, X.w, x4};

#pragma unroll
        for (int k = 0; k < 3; k++) {
            a1a0[k] = fmaf(A.x, e[k], a1a0[k]);
            a1a1[k] = fmaf(f0b, e[k], a1a1[k]);
        }
#pragma unroll
        for (int i = 0; i < 3; i++) a0 = fmaf(x1v[i], e[i], a0);
#pragma unroll
        for (int a = 0; a < 5; a++)
#pragma unroll
            for (int i = 0; i < 3; i++) a2[a] = fmaf(x1v[i], T[a][i], a2[a]);
        if (lane < 16) {
#pragma unroll
            for (int a = 0; a < 5; a++)
#pragma unroll
                for (int k = 0; k < 3; k++) a1b[k] = fmaf(x2v[a], T[a][k], a1b[k]);
        }
    }

    __syncthreads();

    float* ag = sag[warp];
    ag[lane] = a0;
#pragma unroll
    for (int k = 0; k < 3; k++) {
        ag[32 + 4 * lane + k]        = a1a0[k];
        ag[32 + 4 * (lane + 32) + k] = a1a1[k];
    }
    if (lane < 16) {
#pragma unroll
        for (int k = 0; k < 3; k++) ag[288 + 4 * lane + k] = a1b[k];
    }
#pragma unroll
    for (int a = 0; a < 5; a++) ag[352 + 5 * lane + a] = a2[a];
    __syncwarp();

    float* o = out + (size_t)node * DFEAT;
    {
        float y0 = 0.f, y1v = 0.f;
#pragma unroll
        for (int u4 = 0; u4 < 8; u4++) {
            float4 av = *(const float4*)(ag + 4 * u4);
            float a4[4] = {av.x, av.y, av.z, av.w};
#pragma unroll
            for (int j = 0; j < 4; j++) {
                float2 w2 = *(const float2*)(sWL0 + (4 * u4 + j) * 64 + 2 * lane);
                y0  = fmaf(a4[j], w2.x, y0);
                y1v = fmaf(a4[j], w2.y, y1v);
            }
        }
        o[2 * lane]     = y0;
        o[2 * lane + 1] = y1v;
    }
    {
        float y[3] = {0.f, 0.f, 0.f};
#pragma unroll
        for (int u = 0; u < 64; u++) {
            float4 av = *(const float4*)(ag + 32 + 4 * u);
            float lw = sWL1a[u * 32 + lane];
            y[0] = fmaf(av.x, lw, y[0]);
            y[1] = fmaf(av.y, lw, y[1]);
            y[2] = fmaf(av.z, lw, y[2]);
        }
#pragma unroll
        for (int u = 0; u < 16; u++) {
            float4 av = *(const float4*)(ag + 288 + 4 * u);
            float lw = sWL1b[u * 32 + lane];
            y[0] = fmaf(av.x, lw, y[0]);
            y[1] = fmaf(av.y, lw, y[1]);
            y[2] = fmaf(av.z, lw, y[2]);
        }
#pragma unroll
        for (int k = 0; k < 3; k++) o[64 + 3 * lane + k] = y[k];
    }
    {
        int w2i = lane & 15, half = lane >> 4;
        float y[5] = {0.f, 0.f, 0.f, 0.f, 0.f};
#pragma unroll
        for (int uu = 0; uu < 16; uu++) {
            int u = half * 16 + uu;
            float lw = sWL2[u * 16 + w2i];
#pragma unroll
            for (int a = 0; a < 5; a++) y[a] = fmaf(ag[352 + 5 * u + a], lw, y[a]);
        }
#pragma unroll
        for (int a = 0; a < 5; a++) {
            y[a] += __shfl_xor_sync(FULL, y[a], 16);
            if (lane < 16) o[160 + 5 * lane + a] = y[a];
        }
    }
}

// ============================================================================
extern "C" void kernel_launch(void* const* d_in, const int* in_sizes, int n_in,
                              void* d_out, int out_size) {
    const float* feats  = (const float*)d_in[0];
    const float* coords = (const float*)d_in[1];
    const float* W1 = (const float*)d_in[2];
    const float* W2 = (const float*)d_in[3];
    const float* W3 = (const float*)d_in[4];
    const float* W4 = (const float*)d_in[5];
    const float* L0 = (const float*)d_in[6];
    const float* L1 = (const float*)d_in[7];
    const float* L2 = (const float*)d_in[8];
    float* out = (float*)d_out;

    repack_kernel<<<BN / 8, 256>>>(feats, coords);
    fuse_kernel<<<20, 256>>>(W1, W2, W3, W4, L0, L1, L2);
    knn_kernel<<<dim3(NNODES / 64, NB), KTHREADS>>>();
    agg_kernel<<<BN / 8, 256>>>(out);
}

// round 15
// speedup vs baseline: 1.3094x; 1.0301x over previous
#include <cuda_runtime.h>
#include <cstddef>
#include <math_constants.h>

#define NNODES 4096
#define NB 4
#define BN (NNODES * NB)
#define DFEAT 240
#define FXSTRIDE 256
#define KNN 8
#define KTHREADS 512

// Scratch (allocation-free rule: __device__ globals)
__device__ int    g_knn[BN * KNN];
__device__ float4 g_c4[BN];                       // (x,y,z,|c|^2/2)
__device__ float  g_fx[(size_t)BN * FXSTRIDE];    // repacked features
// Fused (W @ L) matrices, output scales baked in
__device__ float g_WL0[32 * 64];
__device__ float g_WL1a[64 * 32];
__device__ float g_WL1b[16 * 32];
__device__ float g_WL2[32 * 16];

// T[a][k] = (Cm[a] . ev)[k]
__device__ __forceinline__ void compute_T(float ex, float ey, float ez, float T[5][3]) {
    const float sc = 0.31622776601683794f;
    const float tc = 0.18257418583505536f;
    T[0][0] = sc * ey;  T[0][1] = sc * ex;   T[0][2] = 0.f;
    T[1][0] = sc * ez;  T[1][1] = 0.f;       T[1][2] = sc * ex;
    T[2][0] = 0.f;      T[2][1] = sc * ez;   T[2][2] = sc * ey;
    T[3][0] = sc * ex;  T[3][1] = -sc * ey;  T[3][2] = 0.f;
    T[4][0] = -tc * ex; T[4][1] = -tc * ey;  T[4][2] = 2.f * tc * ez;
}

// ============================================================================
// Kernel 0: repack features per node (warp per node) + build g_c4.
// ============================================================================
__global__ __launch_bounds__(256) void repack_kernel(
    const float* __restrict__ feats, const float* __restrict__ coords) {
    int warp = threadIdx.x >> 5, lane = threadIdx.x & 31;
    int node = blockIdx.x * 8 + warp;
    const float* f = feats + (size_t)node * DFEAT;
    float* o = g_fx + (size_t)node * FXSTRIDE;
    float4 A;
    A.x = f[lane];
    A.y = f[64 + 3 * lane];
    A.z = f[64 + 3 * lane + 1];
    A.w = f[64 + 3 * lane + 2];
    *(float4*)(o + 4 * lane) = A;
    o[128 + lane] = f[32 + lane];
    if (lane < 16) {
        float4 X;
        X.x = f[160 + 5 * lane];
        X.y = f[160 + 5 * lane + 1];
        X.z = f[160 + 5 * lane + 2];
        X.w = f[160 + 5 * lane + 3];
        *(float4*)(o + 160 + 4 * lane) = X;
        o[224 + lane] = f[160 + 5 * lane + 4];
    }
    if (threadIdx.x < 8) {
        int n2 = blockIdx.x * 8 + threadIdx.x;
        float x = coords[3 * n2], y = coords[3 * n2 + 1], z = coords[3 * n2 + 2];
        g_c4[n2] = make_float4(x, y, z, 0.5f * fmaf(x, x, fmaf(y, y, z * z)));
    }
}

// ============================================================================
// Kernel 1: kNN, 2 QUERIES per warp, 2 candidates per lane per step (64/step).
// Two independent TOP-9s live in lanes 0..8 (sorted ascending, lane 8 =
// worst). No self-exclusion: the query itself has the strict unique min score
// (-|q|^2/2), lands in lane 0; lanes 1..8 = true top-8. Candidate id is
// recovered arithmetically from the ballot lane. Tie = earliest index
// (ballot low->high = index order) — matches jax.lax.top_k.
// ============================================================================
__global__ __launch_bounds__(KTHREADS) void knn_kernel() {
    __shared__ float4 tile[2048];                 // 32KB (chunked: 2 x 2048)
    const unsigned FULL = 0xffffffffu;
    int b = blockIdx.y;
    int warp = threadIdx.x >> 5, lane = threadIdx.x & 31;
    int qbase = (blockIdx.x * 16 + warp) * 2;     // 2 consecutive queries
    int qfbase = b * NNODES + qbase;

    float nqx[2], nqy[2], nqz[2], v[2], worst[2];
    int vid[2];
#pragma unroll
    for (int qi = 0; qi < 2; qi++) {
        float4 qc = g_c4[qfbase + qi];
        nqx[qi] = -qc.x; nqy[qi] = -qc.y; nqz[qi] = -qc.z;
        v[qi] = CUDART_INF_F; vid[qi] = 0x7fffffff; worst[qi] = CUDART_INF_F;
    }

    for (int ch = 0; ch < 2; ch++) {
        int cbase = ch << 11;
        __syncthreads();
        for (int k = threadIdx.x; k < 2048; k += KTHREADS)
            tile[k] = g_c4[b * NNODES + cbase + k];
        __syncthreads();

        for (int s = 0; s < 2048; s += 64) {
            float4 c0 = tile[s + lane];
            float4 c1 = tile[s + 32 + lane];
            float d[2][2];
#pragma unroll
            for (int qi = 0; qi < 2; qi++) {
                d[qi][0] = fmaf(nqx[qi], c0.x, fmaf(nqy[qi], c0.y, fmaf(nqz[qi], c0.z, c0.w)));
                d[qi][1] = fmaf(nqx[qi], c1.x, fmaf(nqy[qi], c1.y, fmaf(nqz[qi], c1.z, c1.w)));
            }
            bool pass = (fminf(d[0][0], d[0][1]) < worst[0])
                      | (fminf(d[1][0], d[1][1]) < worst[1]);
            if (__any_sync(FULL, pass)) {
                int j0 = b * NNODES + cbase + s;  // flat id of lane-0 candidate
#pragma unroll
                for (int qi = 0; qi < 2; qi++) {
#pragma unroll
                    for (int t = 0; t < 2; t++) {
                        unsigned mask = __ballot_sync(FULL, d[qi][t] < worst[qi]);
                        int jt = j0 + (t << 5);
                        while (mask) {
                            int src = __ffs(mask) - 1; mask &= mask - 1;
                            float nb = __shfl_sync(FULL, d[qi][t], src);
                            if (nb < worst[qi]) {         // warp-uniform recheck
                                int ib = jt + src;        // arithmetic id recovery
                                unsigned gt = __ballot_sync(FULL, (lane < 9) && (v[qi] > nb));
                                int p = __ffs(gt) - 1;    // nonzero: lane8 holds worst>nb
                                float vup = __shfl_up_sync(FULL, v[qi], 1);
                                int  iup  = __shfl_up_sync(FULL, vid[qi], 1);
                                if (lane == p)                 { v[qi] = nb;  vid[qi] = ib;  }
                                else if (lane > p && lane < 9) { v[qi] = vup; vid[qi] = iup; }
                                worst[qi] = __shfl_sync(FULL, v[qi], 8);
                            }
                        }
                    }
                }
            }
        }
    }

#pragma unroll
    for (int qi = 0; qi < 2; qi++) {
        if (lane >= 1 && lane < 9)                // lane 0 = self; drop it
            g_knn[(qfbase + qi) * KNN + (lane - 1)] = vid[qi];
    }
}

// ============================================================================
// Kernel 2: fuse W and L matrices (W commutes with aggregation) + bake scales.
// ============================================================================
__global__ __launch_bounds__(256) void fuse_kernel(
    const float* __restrict__ W1, const float* __restrict__ W2,
    const float* __restrict__ W3, const float* __restrict__ W4,
    const float* __restrict__ L0, const float* __restrict__ L1,
    const float* __restrict__ L2) {
    const float c1 = 0.11180339887498949f;
    const float c2 = 0.10206207261596575f;
    const float c3 = 0.39528470752104744f;
    const float c4 = 0.19364916731037085f;
    const float is32 = 0.17677669529663687f;
    int idx = blockIdx.x * 256 + threadIdx.x;
    if (idx < 2048) {                         // WL0 = W2@L0 : (32,64)
        int u = idx >> 6, w2 = idx & 63;
        float acc = 0.f;
        for (int w = 0; w < 64; w++) acc = fmaf(W2[u * 64 + w], L0[w * 64 + w2], acc);
        g_WL0[idx] = (c2 * 0.125f) * acc;
    } else if (idx < 4096) {                  // WL1a = W1@L1 : (64,32)
        int t = idx - 2048, u = t >> 5, w2 = t & 31;
        float acc = 0.f;
        for (int w = 0; w < 32; w++) acc = fmaf(W1[u * 32 + w], L1[w * 32 + w2], acc);
        g_WL1a[t] = (c1 * is32) * acc;
    } else if (idx < 4608) {                  // WL1b = W4@L1 : (16,32)
        int t = idx - 4096, u = t >> 5, w2 = t & 31;
        float acc = 0.f;
        for (int w = 0; w < 32; w++) acc = fmaf(W4[u * 32 + w], L1[w * 32 + w2], acc);
        g_WL1b[t] = (c4 * is32) * acc;
    } else {                                  // WL2 = W3@L2 : (32,16)
        int t = idx - 4608, u = t >> 4, w2 = t & 15;
        float acc = 0.f;
        for (int w = 0; w < 16; w++) acc = fmaf(W3[u * 16 + w], L2[w * 16 + w2], acc);
        g_WL2[t] = (c3 * 0.25f) * acc;
    }
}

// ============================================================================
// Kernel 3: fused aggregation (round-10 version: 48 regs, measured-stable).
// Warp per node. Vectorized coalesced gathers from packed g_fx; neighbor ids
// + coords front-batched. Fused WL linears from shared.
// ============================================================================
__global__ __launch_bounds__(256) void agg_kernel(float* __restrict__ out) {
    __shared__ float sWL0[2048], sWL1a[2048], sWL1b[512], sWL2[512];
    __shared__ float sag[8][440];
    for (int k = threadIdx.x; k < 2048; k += 256) { sWL0[k] = g_WL0[k]; sWL1a[k] = g_WL1a[k]; }
    for (int k = threadIdx.x; k < 512;  k += 256) { sWL1b[k] = g_WL1b[k]; sWL2[k] = g_WL2[k]; }

    int warp = threadIdx.x >> 5, lane = threadIdx.x & 31;
    int node = (blockIdx.x << 3) + warp;
    float4 qc = g_c4[node];

    // front-batch neighbor ids (32B aligned) and edge vectors
    int4 n0 = *(const int4*)(g_knn + node * KNN);
    int4 n1 = *(const int4*)(g_knn + node * KNN + 4);
    int nbr[8] = {n0.x, n0.y, n0.z, n0.w, n1.x, n1.y, n1.z, n1.w};
    float ex[8], ey[8], ez[8];
#pragma unroll
    for (int r = 0; r < 8; r++) {
        float4 cn = g_c4[nbr[r]];
        ex[r] = cn.x - qc.x;
        ey[r] = cn.y - qc.y;
        ez[r] = cn.z - qc.z;
    }

    float a0 = 0.f;
    float a1a0[3] = {0.f, 0.f, 0.f};
    float a1a1[3] = {0.f, 0.f, 0.f};
    float a1b[3]  = {0.f, 0.f, 0.f};
    float a2[5]   = {0.f, 0.f, 0.f, 0.f, 0.f};

#pragma unroll
    for (int r = 0; r < KNN; r++) {
        const float* f = g_fx + (size_t)nbr[r] * FXSTRIDE;
        float4 A = *(const float4*)(f + 4 * lane);        // x0a, x1[0..2]
        float f0b = f[128 + lane];                        // x0b
        float4 X = make_float4(0.f, 0.f, 0.f, 0.f);
        float x4 = 0.f;
        if (lane < 16) {
            X  = *(const float4*)(f + 160 + 4 * lane);    // x2[0..3]
            x4 = f[224 + lane];                           // x2[4]
        }

        float T[5][3];
        compute_T(ex[r], ey[r], ez[r], T);
        float e[3] = {ex[r], ey[r], ez[r]};
        float x1v[3] = {A.y, A.z, A.w};
        float x2v[5] = {X.x, X.y, X.z, X.w, x4};

#pragma unroll
        for (int k = 0; k < 3; k++) {
            a1a0[k] = fmaf(A.x, e[k], a1a0[k]);
            a1a1[k] = fmaf(f0b, e[k], a1a1[k]);
        }
#pragma unroll
        for (int i = 0; i < 3; i++) a0 = fmaf(x1v[i], e[i], a0);
#pragma unroll
        for (int a = 0; a < 5; a++)
#pragma unroll
            for (int i = 0; i < 3; i++) a2[a] = fmaf(x1v[i], T[a][i], a2[a]);
        if (lane < 16) {
#pragma unroll
            for (int a = 0; a < 5; a++)
#pragma unroll
                for (int k = 0; k < 3; k++) a1b[k] = fmaf(x2v[a], T[a][k], a1b[k]);
        }
    }

    __syncthreads();   // sWL ready

    // stage aggregates: [0,32) a0 | 32+3u+k (u<64) a1a | 224+3u+k (u<16) a1b | 272+5u+a a2
    float* ag = sag[warp];
    ag[lane] = a0;
#pragma unroll
    for (int k = 0; k < 3; k++) {
        ag[32 + 3 * lane + k]        = a1a0[k];
        ag[32 + 3 * (lane + 32) + k] = a1a1[k];
    }
    if (lane < 16) {
#pragma unroll
        for (int k = 0; k < 3; k++) ag[224 + 3 * lane + k] = a1b[k];
    }
#pragma unroll
    for (int a = 0; a < 5; a++) ag[272 + 5 * lane + a] = a2[a];
    __syncwarp();

    float* o = out + (size_t)node * DFEAT;
    {   // y0[w'] = sum_u a0[u] WL0[u,w']   (w' = 2lane, 2lane+1)
        float y0 = 0.f, y1v = 0.f;
#pragma unroll
        for (int u = 0; u < 32; u++) {
            float av = ag[u];
            y0  = fmaf(av, sWL0[u * 64 + 2 * lane],     y0);
            y1v = fmaf(av, sWL0[u * 64 + 2 * lane + 1], y1v);
        }
        o[2 * lane]     = y0;
        o[2 * lane + 1] = y1v;
    }
    {   // y1[w',k] = sum_{u<64} a1a[u,k] WL1a[u,w'] + sum_{u<16} a1b[u,k] WL1b[u,w']
        float y[3] = {0.f, 0.f, 0.f};
#pragma unroll
        for (int u = 0; u < 64; u++) {
            float lw = sWL1a[u * 32 + lane];
#pragma unroll
            for (int k = 0; k < 3; k++) y[k] = fmaf(ag[32 + 3 * u + k], lw, y[k]);
        }
#pragma unroll
        for (int u = 0; u < 16; u++) {
            float lw = sWL1b[u * 32 + lane];
#pragma unroll
            for (int k = 0; k < 3; k++) y[k] = fmaf(ag[224 + 3 * u + k], lw, y[k]);
        }
#pragma unroll
        for (int k = 0; k < 3; k++) o[64 + 3 * lane + k] = y[k];
    }
    if (lane < 16) {   // y2[w',a] = sum_u a2[u,a] WL2[u,w']
        float y[5] = {0.f, 0.f, 0.f, 0.f, 0.f};
#pragma unroll
        for (int u = 0; u < 32; u++) {
            float lw = sWL2[u * 16 + lane];
#pragma unroll
            for (int a = 0; a < 5; a++) y[a] = fmaf(ag[272 + 5 * u + a], lw, y[a]);
        }
#pragma unroll
        for (int a = 0; a < 5; a++) o[160 + 5 * lane + a] = y[a];
    }
}

// ============================================================================
extern "C" void kernel_launch(void* const* d_in, const int* in_sizes, int n_in,
                              void* d_out, int out_size) {
    const float* feats  = (const float*)d_in[0];
    const float* coords = (const float*)d_in[1];
    const float* W1 = (const float*)d_in[2];
    const float* W2 = (const float*)d_in[3];
    const float* W3 = (const float*)d_in[4];
    const float* W4 = (const float*)d_in[5];
    const float* L0 = (const float*)d_in[6];
    const float* L1 = (const float*)d_in[7];
    const float* L2 = (const float*)d_in[8];
    float* out = (float*)d_out;

    repack_kernel<<<BN / 8, 256>>>(feats, coords);
    fuse_kernel<<<20, 256>>>(W1, W2, W3, W4, L0, L1, L2);
    knn_kernel<<<dim3(NNODES / 32, NB), KTHREADS>>>();
    agg_kernel<<<BN / 8, 256>>>(out);
}